// round 14
// baseline (speedup 1.0000x reference)
#include <cuda_runtime.h>
#include <cuda_fp16.h>
#include <math.h>
#include <cstdint>

#define C_CH 128
#define VN 10
#define NB_TOT 32768
#define R_TOT (NB_TOT * VN)     // 327680 rows
#define N3 384
#define HEADS 8
#define DH 16
#define BN_EPS 1e-5f

#define STATS_BLOCKS 512
#define ROWS_PER_STAT (R_TOT / STATS_BLOCKS)

#define BPC 6
#define MROWS (BPC * VN)        // 60 valid rows, padded to 64
#define THREADS 512
#define TILES ((NB_TOT + BPC - 1) / BPC)   // 5462
#define GRID_P 148

// smem layout (byte offsets) — ~200KB, 1 CTA/SM, 16 warps
#define WALL_OFF  0u            // 4 chunks x 32KB packed fp16 weights (W1 c0,c1,c2, W2)
#define XS_OFF    131072u       // A-pack fp16: 16384 B (x tile, later P)
#define QKV_OFF   147456u       // [64][392] halves = 50176 B
#define QKV_STR   392
#define BIAS1_OFF 197632u       // 384 f32
#define BOUT_OFF  199168u       // 128 f32
#define MASK_OFF  199680u       // 100 f32
#define SMEM_TOTAL 200192u

// ---------------- device scratch ----------------
__device__ float g_psum[STATS_BLOCKS][C_CH];
__device__ float g_psumsq[STATS_BLOCKS][C_CH];
__device__ float g_a[C_CH];
__device__ float g_b[C_CH];
__device__ float g_bias1[N3];
__device__ __align__(16) __half g_w1h[3 * 16384];  // packed fp16 folded W1
__device__ __align__(16) __half g_w2h[16384];      // packed fp16 W2

// ---------------- helpers ----------------
__device__ __forceinline__ uint32_t smem_u32(const void* p) {
    uint32_t a;
    asm("{ .reg .u64 t; cvta.to.shared.u64 t, %1; cvt.u32.u64 %0, t; }" : "=r"(a) : "l"(p));
    return a;
}
#define CP_ASYNC16(dst, src) \
    asm volatile("cp.async.ca.shared.global [%0], [%1], 16;" :: "r"(dst), "l"(src) : "memory")
#define CP_COMMIT() asm volatile("cp.async.commit_group;" ::: "memory")
#define CP_WAIT(n)  asm volatile("cp.async.wait_group %0;" :: "n"(n) : "memory")

// fp16 MMA, fp32 accumulate: m16n8k16
__device__ __forceinline__ void mma16(float* d, const float4& a, uint32_t b0, uint32_t b1) {
    asm volatile(
        "mma.sync.aligned.m16n8k16.row.col.f32.f16.f16.f32 "
        "{%0,%1,%2,%3},{%4,%5,%6,%7},{%8,%9},{%0,%1,%2,%3};"
        : "+f"(d[0]), "+f"(d[1]), "+f"(d[2]), "+f"(d[3])
        : "r"(__float_as_uint(a.x)), "r"(__float_as_uint(a.y)),
          "r"(__float_as_uint(a.z)), "r"(__float_as_uint(a.w)),
          "r"(b0), "r"(b1));
}

// W-pack half index within one chunk (k in [0,128), n in [0,128)) — unchanged from R13
__device__ __forceinline__ int wpack_h_idx(int k, int n) {
    const int ksg = k >> 4;
    const int strip = ksg >> 2, kks = ksg & 3;
    const int k_in = k & 15, kh = k_in >> 3, klo = k_in & 1, t = (k_in >> 1) & 3;
    const int wn = n >> 5, nr = n & 31, nt = nr >> 3, g = nr & 7;
    const int unit = ((wn * 4 + kks) * 2 + kh) * 32 + g * 4 + t;
    return strip * 8192 + unit * 8 + nt * 2 + klo;
}

// load 8 consecutive halves (16B aligned) -> 8 floats
__device__ __forceinline__ void ld8(const __half* p, float* f) {
    float4 r = *reinterpret_cast<const float4*>(p);
    uint32_t u0 = __float_as_uint(r.x), u1 = __float_as_uint(r.y);
    uint32_t u2 = __float_as_uint(r.z), u3 = __float_as_uint(r.w);
    float2 f0 = __half22float2(*reinterpret_cast<__half2*>(&u0));
    float2 f1 = __half22float2(*reinterpret_cast<__half2*>(&u1));
    float2 f2 = __half22float2(*reinterpret_cast<__half2*>(&u2));
    float2 f3 = __half22float2(*reinterpret_cast<__half2*>(&u3));
    f[0] = f0.x; f[1] = f0.y; f[2] = f1.x; f[3] = f1.y;
    f[4] = f2.x; f[5] = f2.y; f[6] = f3.x; f[7] = f3.y;
}

// pack one float4 of x (row m, cols gq*4..+3) into the 16-row-strip A-pack
__device__ __forceinline__ void pack_x4(__half* xsh, int m, int gq, const float4& v) {
    const int s = m >> 4, r16 = m & 15;
    const int gL = r16 & 7, iL = r16 >> 3;
    const int col0 = gq * 4;
    const int kk = col0 >> 4;
    const int k_in0 = col0 & 15;
    const int khi = k_in0 >> 3;
    const int t0 = (k_in0 >> 1) & 3;
    const int r = iL + 2 * khi;
    const int ubase = (s * 8 + kk) * 32 + gL * 4;
    *reinterpret_cast<__half2*>(xsh + (ubase + t0) * 8 + r * 2) = __floats2half2_rn(v.x, v.y);
    *reinterpret_cast<__half2*>(xsh + (ubase + t0 + 1) * 8 + r * 2) = __floats2half2_rn(v.z, v.w);
}

// ---------------- kernel 1: BN partial stats ----------------
__global__ __launch_bounds__(128)
void ga_stats_kernel(const float* __restrict__ x) {
    const int c = threadIdx.x;
    const float* p = x + (size_t)blockIdx.x * ROWS_PER_STAT * C_CH + c;
    float s = 0.f, s2 = 0.f;
#pragma unroll 8
    for (int r = 0; r < ROWS_PER_STAT; ++r) {
        float v = p[(size_t)r * C_CH];
        s += v;
        s2 = fmaf(v, v, s2);
    }
    g_psum[blockIdx.x][c] = s;
    g_psumsq[blockIdx.x][c] = s2;
}

// ---------------- kernel 2: finalize stats ----------------
__global__ __launch_bounds__(128)
void ga_prep_kernel(const float* __restrict__ gamma, const float* __restrict__ beta) {
    const int c = threadIdx.x;
    float s = 0.f, s2 = 0.f;
    for (int b = 0; b < STATS_BLOCKS; ++b) { s += g_psum[b][c]; s2 += g_psumsq[b][c]; }
    const float invR = 1.0f / (float)R_TOT;
    float mean = s * invR;
    float var = s2 * invR - mean * mean;
    float rstd = rsqrtf(var + BN_EPS);
    float a = gamma[c] * rstd;
    g_a[c] = a;
    g_b[c] = beta[c] - mean * a;
}

// ---------------- kernel 3: fold W1 (BN) + W2 into packed fp16 layouts + bias1 ----
__global__ __launch_bounds__(128)
void ga_fold_kernel(const float* __restrict__ w_qkv, const float* __restrict__ w_out) {
    if (blockIdx.x < N3) {
        const int n3 = blockIdx.x;
        const int k = threadIdx.x;
        float wv = w_qkv[(size_t)k * N3 + n3];
        const int chunk = n3 >> 7, n = n3 & 127;
        g_w1h[chunk * 16384 + wpack_h_idx(k, n)] = __float2half_rn(g_a[k] * wv);
        __shared__ float red[128];
        red[k] = g_b[k] * wv;
        __syncthreads();
        for (int off = 64; off > 0; off >>= 1) {
            if (k < off) red[k] += red[k + off];
            __syncthreads();
        }
        if (k == 0) g_bias1[n3] = red[0];
    } else {
        const int k = blockIdx.x - N3;   // 0..127
        const int n = threadIdx.x;       // 0..127
        g_w2h[wpack_h_idx(k, n)] = __float2half_rn(w_out[(size_t)k * C_CH + n]);
    }
}

// ---------------- persistent main kernel ----------------
__device__ __forceinline__ void gemm_half(
    const float4* __restrict__ xp, const float4* __restrict__ wp,
    int h, int wm, int wn, int lane, float acc[4][4])
{
#pragma unroll
    for (int kks = 0; kks < 4; ++kks) {
        const int kk = h * 4 + kks;
        const float4 a = xp[(wm * 8 + kk) * 32 + lane];
        const float4 blo = wp[((wn * 4 + kks) * 2 + 0) * 32 + lane];
        const float4 bhi = wp[((wn * 4 + kks) * 2 + 1) * 32 + lane];
        mma16(acc[0], a, __float_as_uint(blo.x), __float_as_uint(bhi.x));
        mma16(acc[1], a, __float_as_uint(blo.y), __float_as_uint(bhi.y));
        mma16(acc[2], a, __float_as_uint(blo.z), __float_as_uint(bhi.z));
        mma16(acc[3], a, __float_as_uint(blo.w), __float_as_uint(bhi.w));
    }
}

__global__ __launch_bounds__(THREADS, 1)
void ga_main_kernel(const float* __restrict__ x,
                    const float* __restrict__ b_out,
                    const float* __restrict__ mask,
                    float* __restrict__ out)
{
    extern __shared__ char smem[];
    __half* xsh = (__half*)(smem + XS_OFF);
    __half* qkvh = (__half*)(smem + QKV_OFF);
    float* bias1s = (float*)(smem + BIAS1_OFF);
    float* bouts = (float*)(smem + BOUT_OFF);
    float* mk = (float*)(smem + MASK_OFF);
    const float4* xp = (const float4*)(smem + XS_OFF);

    const int tid = threadIdx.x;
    const int lane = tid & 31;
    const int wid = tid >> 5;
    const int wm = wid & 3;        // 4 M-strips of 16
    const int wn = wid >> 2;       // 4 N-strips of 32
    const int g = lane >> 2;
    const int tig = lane & 3;

    // ---- prologue: all weights -> smem (128KB), consts, first x tile ----
    {
        const uint32_t dstbase = smem_u32(smem + WALL_OFF);
#pragma unroll
        for (int j = 0; j < 16; ++j) {
            const int u = tid + j * THREADS;    // 8192 units of 16B
            const __half* src = (u < 6144) ? (g_w1h + u * 8) : (g_w2h + (u - 6144) * 8);
            CP_ASYNC16(dstbase + (uint32_t)u * 16u, src);
        }
        CP_COMMIT();
    }
    for (int e = tid; e < N3; e += THREADS) bias1s[e] = g_bias1[e];
    for (int e = tid; e < C_CH; e += THREADS) bouts[e] = b_out[e];
    for (int e = tid; e < VN * VN; e += THREADS) mk[e] = mask[e];

    int t = blockIdx.x;
    // first x tile -> registers then pack
    {
        const float4* xv = reinterpret_cast<const float4*>(x);
        const int row0 = t * MROWS;
        const int vr = min(MROWS, R_TOT - row0);
        float4 nx[4];
#pragma unroll
        for (int j = 0; j < 4; ++j) {
            const int idx = tid + j * THREADS;
            const int m = idx >> 5, gq = idx & 31;
            nx[j] = (m < vr) ? xv[(size_t)(row0 + m) * 32 + gq]
                             : make_float4(0.f, 0.f, 0.f, 0.f);
        }
        CP_WAIT(0);
#pragma unroll
        for (int j = 0; j < 4; ++j) {
            const int idx = tid + j * THREADS;
            pack_x4(xsh, idx >> 5, idx & 31, nx[j]);
        }
    }
    __syncthreads();

    // ---- persistent tile loop ----
    for (; t < TILES; t += GRID_P) {
        const int row0 = t * MROWS;
        const int valid_rows = min(MROWS, R_TOT - row0);
        const int valid_items = min(BPC, NB_TOT - t * BPC);

        // ---- GEMM1: qkv = x @ W1' + bias1 (weights resident) ----
#pragma unroll 1
        for (int c = 0; c < 3; ++c) {
            float acc[4][4];
#pragma unroll
            for (int nt = 0; nt < 4; ++nt) {
                const int col = c * 128 + wn * 32 + nt * 8 + tig * 2;
                acc[nt][0] = bias1s[col]; acc[nt][1] = bias1s[col + 1];
                acc[nt][2] = acc[nt][0];  acc[nt][3] = acc[nt][1];
            }
#pragma unroll
            for (int h = 0; h < 2; ++h)
                gemm_half(xp, (const float4*)(smem + WALL_OFF + c * 32768 + h * 16384),
                          h, wm, wn, lane, acc);
            const int row = wm * 16 + g;
#pragma unroll
            for (int nt = 0; nt < 4; ++nt) {
                const int col = c * 128 + wn * 32 + nt * 8 + tig * 2;
                *reinterpret_cast<__half2*>(qkvh + row * QKV_STR + col) =
                    __floats2half2_rn(acc[nt][0], acc[nt][1]);
                *reinterpret_cast<__half2*>(qkvh + (row + 8) * QKV_STR + col) =
                    __floats2half2_rn(acc[nt][2], acc[nt][3]);
            }
        }
        __syncthreads();

        // ---- prefetch next tile's x into registers (latency hidden by attention) ----
        float4 nx[4];
        const int tn = t + GRID_P;
        {
            const float4* xv = reinterpret_cast<const float4*>(x);
            const int nrow0 = tn * MROWS;
            const int nvr = (tn < TILES) ? min(MROWS, R_TOT - nrow0) : 0;
#pragma unroll
            for (int j = 0; j < 4; ++j) {
                const int idx = tid + j * THREADS;
                const int m = idx >> 5, gq = idx & 31;
                nx[j] = (m < nvr) ? xv[(size_t)(nrow0 + m) * 32 + gq]
                                  : make_float4(0.f, 0.f, 0.f, 0.f);
            }
        }

        // ---- attention (fp32 math, fp16 storage); writes P into xs A-pack ----
        if (tid < BPC * HEADS * VN) {
            const int it = tid;
            const int b = it / (HEADS * VN);
            const int rem = it - b * (HEADS * VN);
            const int h = rem / VN;
            const int i = rem - h * VN;
            if (b < valid_items) {
                const int h16 = h * DH;
                const int ri = b * VN + i;
                float qv[DH];
                ld8(qkvh + ri * QKV_STR + h16, qv);
                ld8(qkvh + ri * QKV_STR + h16 + 8, qv + 8);
                float dots[VN];
                float mx = -1e30f;
#pragma unroll
                for (int j = 0; j < VN; ++j) {
                    float kvv[DH];
                    const __half* kr = qkvh + (b * VN + j) * QKV_STR + 128 + h16;
                    ld8(kr, kvv);
                    ld8(kr + 8, kvv + 8);
                    float s = 0.f;
#pragma unroll
                    for (int d = 0; d < DH; ++d) s = fmaf(qv[d], kvv[d], s);
                    float v = s * 0.25f * mk[i * VN + j];
                    dots[j] = v;
                    mx = fmaxf(mx, v);
                }
                float ssum = 0.f;
#pragma unroll
                for (int j = 0; j < VN; ++j) { dots[j] = __expf(dots[j] - mx); ssum += dots[j]; }
                const float inv = 1.0f / ssum;
                float o[DH];
#pragma unroll
                for (int d = 0; d < DH; ++d) o[d] = 0.f;
#pragma unroll
                for (int j = 0; j < VN; ++j) {
                    float vv[DH];
                    const __half* vr = qkvh + (b * VN + j) * QKV_STR + 256 + h16;
                    ld8(vr, vv);
                    ld8(vr + 8, vv + 8);
                    const float w = dots[j];
#pragma unroll
                    for (int d = 0; d < DH; ++d) o[d] = fmaf(w, vv[d], o[d]);
                }
                // write P into A-pack: row ri, cols h16+d (kk = h)
                const int s = ri >> 4, r16 = ri & 15;
                const int gL = r16 & 7, iL = r16 >> 3;
                const int ubase = (s * 8 + h) * 32 + gL * 4;
#pragma unroll
                for (int d = 0; d < DH; d += 2) {
                    const int khi = d >> 3;
                    const int tt = (d >> 1) & 3;
                    const int r = iL + 2 * khi;
                    *reinterpret_cast<__half2*>(xsh + (ubase + tt) * 8 + r * 2) =
                        __floats2half2_rn(o[d] * inv, o[d + 1] * inv);
                }
            }
        }
        __syncthreads();

        // ---- GEMM2: out = P @ W2 + b_out ----
        {
            float acc[4][4];
#pragma unroll
            for (int nt = 0; nt < 4; ++nt) {
                const int col = wn * 32 + nt * 8 + tig * 2;
                acc[nt][0] = bouts[col]; acc[nt][1] = bouts[col + 1];
                acc[nt][2] = acc[nt][0]; acc[nt][3] = acc[nt][1];
            }
#pragma unroll
            for (int h = 0; h < 2; ++h)
                gemm_half(xp, (const float4*)(smem + WALL_OFF + 3 * 32768 + h * 16384),
                          h, wm, wn, lane, acc);
            const int row = wm * 16 + g;
#pragma unroll
            for (int nt = 0; nt < 4; ++nt) {
                const int col = wn * 32 + nt * 8 + tig * 2;
                if (row < valid_rows) {
                    *reinterpret_cast<float2*>(&out[(size_t)(row0 + row) * C_CH + col]) =
                        make_float2(acc[nt][0], acc[nt][1]);
                }
                if (row + 8 < valid_rows) {
                    *reinterpret_cast<float2*>(&out[(size_t)(row0 + row + 8) * C_CH + col]) =
                        make_float2(acc[nt][2], acc[nt][3]);
                }
            }
        }
        __syncthreads();   // all reads of xs (P) done before overwrite

        // ---- pack next x into xs ----
        if (tn < TILES) {
#pragma unroll
            for (int j = 0; j < 4; ++j) {
                const int idx = tid + j * THREADS;
                pack_x4(xsh, idx >> 5, idx & 31, nx[j]);
            }
        }
        __syncthreads();   // pack visible before next GEMM1
    }
}

// ---------------- launch ----------------
extern "C" void kernel_launch(void* const* d_in, const int* in_sizes, int n_in,
                              void* d_out, int out_size) {
    (void)in_sizes; (void)n_in; (void)out_size;
    const float* x     = (const float*)d_in[0];
    const float* gamma = (const float*)d_in[1];
    const float* beta  = (const float*)d_in[2];
    const float* w_qkv = (const float*)d_in[3];
    const float* w_out = (const float*)d_in[4];
    const float* b_out = (const float*)d_in[5];
    const float* mask  = (const float*)d_in[6];
    float* out = (float*)d_out;

    cudaFuncSetAttribute(ga_main_kernel,
                         cudaFuncAttributeMaxDynamicSharedMemorySize,
                         (int)SMEM_TOTAL);

    ga_stats_kernel<<<STATS_BLOCKS, 128>>>(x);
    ga_prep_kernel<<<1, 128>>>(gamma, beta);
    ga_fold_kernel<<<N3 + C_CH, 128>>>(w_qkv, w_out);
    ga_main_kernel<<<GRID_P, THREADS, SMEM_TOTAL>>>(x, b_out, mask, out);
}

// round 17
// speedup vs baseline: 1.0677x; 1.0677x over previous
#include <cuda_runtime.h>
#include <cuda_fp16.h>
#include <math.h>
#include <cstdint>

#define C_CH 128
#define VN 10
#define NB_TOT 32768
#define R_TOT (NB_TOT * VN)     // 327680 rows
#define N3 384
#define HEADS 8
#define DH 16
#define BN_EPS 1e-5f

#define STATS_BLOCKS 1024
#define ROWS_PER_STAT (R_TOT / STATS_BLOCKS)   // 320

#define BPC 6
#define MROWS (BPC * VN)        // 60 valid rows, padded to 64
#define THREADS 512
#define TILES ((NB_TOT + BPC - 1) / BPC)   // 5462
#define GRID_P 148

// smem layout (byte offsets)
#define WALL_OFF  0u            // 4 chunks x 32KB packed fp16 weights (W1 c0,c1,c2, W2)
#define XS_OFF    131072u       // 2 x 16KB A-pack fp16 (double-buffered x/P)
#define XSB_B     16384u
#define QKV_OFF   163840u       // [64][392] halves = 50176 B
#define QKV_STR   392
#define BIAS1_OFF 214016u       // 384 f32
#define BOUT_OFF  215552u       // 128 f32
#define MASK_OFF  216064u       // 100 f32
#define SMEM_TOTAL 216576u

// ---------------- device scratch ----------------
__device__ float g_psum[STATS_BLOCKS][C_CH];
__device__ float g_psumsq[STATS_BLOCKS][C_CH];
__device__ float g_a[C_CH];
__device__ float g_b[C_CH];
__device__ float g_bias1[N3];
__device__ __align__(16) __half g_w1h[3 * 16384];  // packed fp16 folded W1
__device__ __align__(16) __half g_w2h[16384];      // packed fp16 W2

// ---------------- helpers ----------------
__device__ __forceinline__ uint32_t smem_u32(const void* p) {
    uint32_t a;
    asm("{ .reg .u64 t; cvta.to.shared.u64 t, %1; cvt.u32.u64 %0, t; }" : "=r"(a) : "l"(p));
    return a;
}
#define CP_ASYNC16(dst, src) \
    asm volatile("cp.async.ca.shared.global [%0], [%1], 16;" :: "r"(dst), "l"(src) : "memory")
#define CP_COMMIT() asm volatile("cp.async.commit_group;" ::: "memory")
#define CP_WAIT(n)  asm volatile("cp.async.wait_group %0;" :: "n"(n) : "memory")

// fp16 MMA, fp32 accumulate: m16n8k16
__device__ __forceinline__ void mma16(float* d, const float4& a, uint32_t b0, uint32_t b1) {
    asm volatile(
        "mma.sync.aligned.m16n8k16.row.col.f32.f16.f16.f32 "
        "{%0,%1,%2,%3},{%4,%5,%6,%7},{%8,%9},{%0,%1,%2,%3};"
        : "+f"(d[0]), "+f"(d[1]), "+f"(d[2]), "+f"(d[3])
        : "r"(__float_as_uint(a.x)), "r"(__float_as_uint(a.y)),
          "r"(__float_as_uint(a.z)), "r"(__float_as_uint(a.w)),
          "r"(b0), "r"(b1));
}

// W-pack half index within one chunk (k in [0,128), n in [0,128))
__device__ __forceinline__ int wpack_h_idx(int k, int n) {
    const int ksg = k >> 4;
    const int strip = ksg >> 2, kks = ksg & 3;
    const int k_in = k & 15, kh = k_in >> 3, klo = k_in & 1, t = (k_in >> 1) & 3;
    const int wn = n >> 5, nr = n & 31, nt = nr >> 3, g = nr & 7;
    const int unit = ((wn * 4 + kks) * 2 + kh) * 32 + g * 4 + t;
    return strip * 8192 + unit * 8 + nt * 2 + klo;
}

// load 8 consecutive halves (16B aligned) -> 8 floats
__device__ __forceinline__ void ld8(const __half* p, float* f) {
    float4 r = *reinterpret_cast<const float4*>(p);
    uint32_t u0 = __float_as_uint(r.x), u1 = __float_as_uint(r.y);
    uint32_t u2 = __float_as_uint(r.z), u3 = __float_as_uint(r.w);
    float2 f0 = __half22float2(*reinterpret_cast<__half2*>(&u0));
    float2 f1 = __half22float2(*reinterpret_cast<__half2*>(&u1));
    float2 f2 = __half22float2(*reinterpret_cast<__half2*>(&u2));
    float2 f3 = __half22float2(*reinterpret_cast<__half2*>(&u3));
    f[0] = f0.x; f[1] = f0.y; f[2] = f1.x; f[3] = f1.y;
    f[4] = f2.x; f[5] = f2.y; f[6] = f3.x; f[7] = f3.y;
}

// pack one float4 of x (row m, cols gq*4..+3) into the 16-row-strip A-pack
__device__ __forceinline__ void pack_x4(__half* xsh, int m, int gq, const float4& v) {
    const int s = m >> 4, r16 = m & 15;
    const int gL = r16 & 7, iL = r16 >> 3;
    const int col0 = gq * 4;
    const int kk = col0 >> 4;
    const int k_in0 = col0 & 15;
    const int khi = k_in0 >> 3;
    const int t0 = (k_in0 >> 1) & 3;
    const int r = iL + 2 * khi;
    const int ubase = (s * 8 + kk) * 32 + gL * 4;
    *reinterpret_cast<__half2*>(xsh + (ubase + t0) * 8 + r * 2) = __floats2half2_rn(v.x, v.y);
    *reinterpret_cast<__half2*>(xsh + (ubase + t0 + 1) * 8 + r * 2) = __floats2half2_rn(v.z, v.w);
}

// ---------------- kernel 1: BN partial stats ----------------
__global__ __launch_bounds__(128)
void ga_stats_kernel(const float* __restrict__ x) {
    const int c = threadIdx.x;
    const float* p = x + (size_t)blockIdx.x * ROWS_PER_STAT * C_CH + c;
    float s = 0.f, s2 = 0.f;
#pragma unroll 8
    for (int r = 0; r < ROWS_PER_STAT; ++r) {
        float v = p[(size_t)r * C_CH];
        s += v;
        s2 = fmaf(v, v, s2);
    }
    g_psum[blockIdx.x][c] = s;
    g_psumsq[blockIdx.x][c] = s2;
}

// ---------------- kernel 2: finalize stats ----------------
__global__ __launch_bounds__(128)
void ga_prep_kernel(const float* __restrict__ gamma, const float* __restrict__ beta) {
    const int c = threadIdx.x;
    float s = 0.f, s2 = 0.f;
#pragma unroll 8
    for (int b = 0; b < STATS_BLOCKS; ++b) { s += g_psum[b][c]; s2 += g_psumsq[b][c]; }
    const float invR = 1.0f / (float)R_TOT;
    float mean = s * invR;
    float var = s2 * invR - mean * mean;
    float rstd = rsqrtf(var + BN_EPS);
    float a = gamma[c] * rstd;
    g_a[c] = a;
    g_b[c] = beta[c] - mean * a;
}

// ---------------- kernel 3: fold W1 (BN) + W2 into packed fp16 layouts + bias1 ----
__global__ __launch_bounds__(128)
void ga_fold_kernel(const float* __restrict__ w_qkv, const float* __restrict__ w_out) {
    if (blockIdx.x < N3) {
        const int n3 = blockIdx.x;
        const int k = threadIdx.x;
        float wv = w_qkv[(size_t)k * N3 + n3];
        const int chunk = n3 >> 7, n = n3 & 127;
        g_w1h[chunk * 16384 + wpack_h_idx(k, n)] = __float2half_rn(g_a[k] * wv);
        __shared__ float red[128];
        red[k] = g_b[k] * wv;
        __syncthreads();
        for (int off = 64; off > 0; off >>= 1) {
            if (k < off) red[k] += red[k + off];
            __syncthreads();
        }
        if (k == 0) g_bias1[n3] = red[0];
    } else {
        const int k = blockIdx.x - N3;   // 0..127
        const int n = threadIdx.x;       // 0..127
        g_w2h[wpack_h_idx(k, n)] = __float2half_rn(w_out[(size_t)k * C_CH + n]);
    }
}

// ---------------- persistent main kernel ----------------
// GEMM2 helper: 16 warps, M16N32 warp tiles (as R14)
__device__ __forceinline__ void gemm2_half(
    const float4* __restrict__ xp, const float4* __restrict__ wp,
    int h, int wm, int wn, int lane, float acc[4][4])
{
#pragma unroll
    for (int kks = 0; kks < 4; ++kks) {
        const int kk = h * 4 + kks;
        const float4 a = xp[(wm * 8 + kk) * 32 + lane];
        const float4 blo = wp[((wn * 4 + kks) * 2 + 0) * 32 + lane];
        const float4 bhi = wp[((wn * 4 + kks) * 2 + 1) * 32 + lane];
        mma16(acc[0], a, __float_as_uint(blo.x), __float_as_uint(bhi.x));
        mma16(acc[1], a, __float_as_uint(blo.y), __float_as_uint(bhi.y));
        mma16(acc[2], a, __float_as_uint(blo.z), __float_as_uint(bhi.z));
        mma16(acc[3], a, __float_as_uint(blo.w), __float_as_uint(bhi.w));
    }
}

__global__ __launch_bounds__(THREADS, 1)
void ga_main_kernel(const float* __restrict__ x,
                    const float* __restrict__ b_out,
                    const float* __restrict__ mask,
                    float* __restrict__ out)
{
    extern __shared__ char smem[];
    __half* qkvh = (__half*)(smem + QKV_OFF);
    float* bias1s = (float*)(smem + BIAS1_OFF);
    float* bouts = (float*)(smem + BOUT_OFF);
    float* mk = (float*)(smem + MASK_OFF);

    const int tid = threadIdx.x;
    const int lane = tid & 31;
    const int wid = tid >> 5;
    const int g = lane >> 2;
    const int tig = lane & 3;
    const float4* xv = reinterpret_cast<const float4*>(x);

    // ---- prologue: all weights -> smem (128KB), consts ----
    {
        const uint32_t dstbase = smem_u32(smem + WALL_OFF);
#pragma unroll
        for (int j = 0; j < 16; ++j) {
            const int u = tid + j * THREADS;    // 8192 units of 16B
            const __half* src = (u < 6144) ? (g_w1h + u * 8) : (g_w2h + (u - 6144) * 8);
            CP_ASYNC16(dstbase + (uint32_t)u * 16u, src);
        }
        CP_COMMIT();
    }
    for (int e = tid; e < N3; e += THREADS) bias1s[e] = g_bias1[e];
    for (int e = tid; e < C_CH; e += THREADS) bouts[e] = b_out[e];
    for (int e = tid; e < VN * VN; e += THREADS) mk[e] = mask[e];

    // first x tile -> buffer 0 (all threads)
    {
        const int row0 = blockIdx.x * MROWS;
        const int vr = min(MROWS, R_TOT - row0);
        __half* xs0 = (__half*)(smem + XS_OFF);
        float4 nx[4];
#pragma unroll
        for (int j = 0; j < 4; ++j) {
            const int idx = tid + j * THREADS;
            const int m = idx >> 5, gq = idx & 31;
            nx[j] = (m < vr) ? xv[(size_t)(row0 + m) * 32 + gq]
                             : make_float4(0.f, 0.f, 0.f, 0.f);
        }
        CP_WAIT(0);
#pragma unroll
        for (int j = 0; j < 4; ++j) {
            const int idx = tid + j * THREADS;
            pack_x4(xs0, idx >> 5, idx & 31, nx[j]);
        }
    }
    __syncthreads();

    // ---- persistent tile loop ----
    int it = 0;
    for (int t = blockIdx.x; t < TILES; t += GRID_P, ++it) {
        const int cur = it & 1;
        __half* xsc = (__half*)(smem + XS_OFF + (uint32_t)cur * XSB_B);
        const float4* xpc = (const float4*)xsc;
        const int row0 = t * MROWS;
        const int valid_rows = min(MROWS, R_TOT - row0);
        const int valid_items = min(BPC, NB_TOT - t * BPC);

        // ---- GEMM1 (warps 0-11, M64N32) || next-x load+pack (warps 12-15) ----
        if (wid < 12) {
            const int chunk = wid >> 2;
            const int wn1 = wid & 3;
            float acc[4][4][4];
#pragma unroll
            for (int nt = 0; nt < 4; ++nt) {
                const int col = chunk * 128 + wn1 * 32 + nt * 8 + tig * 2;
                const float b0 = bias1s[col], b1 = bias1s[col + 1];
#pragma unroll
                for (int s = 0; s < 4; ++s) {
                    acc[s][nt][0] = b0; acc[s][nt][1] = b1;
                    acc[s][nt][2] = b0; acc[s][nt][3] = b1;
                }
            }
#pragma unroll
            for (int h = 0; h < 2; ++h) {
                const float4* wp = (const float4*)(smem + WALL_OFF + chunk * 32768 + h * 16384);
#pragma unroll
                for (int kks = 0; kks < 4; ++kks) {
                    const int kk = h * 4 + kks;
                    float4 a0 = xpc[(0 * 8 + kk) * 32 + lane];
                    float4 a1 = xpc[(1 * 8 + kk) * 32 + lane];
                    float4 a2 = xpc[(2 * 8 + kk) * 32 + lane];
                    float4 a3 = xpc[(3 * 8 + kk) * 32 + lane];
                    const float4 blo = wp[((wn1 * 4 + kks) * 2 + 0) * 32 + lane];
                    const float4 bhi = wp[((wn1 * 4 + kks) * 2 + 1) * 32 + lane];
                    const uint32_t bx0 = __float_as_uint(blo.x), bx1 = __float_as_uint(bhi.x);
                    const uint32_t by0 = __float_as_uint(blo.y), by1 = __float_as_uint(bhi.y);
                    const uint32_t bz0 = __float_as_uint(blo.z), bz1 = __float_as_uint(bhi.z);
                    const uint32_t bw0 = __float_as_uint(blo.w), bw1 = __float_as_uint(bhi.w);
                    mma16(acc[0][0], a0, bx0, bx1); mma16(acc[0][1], a0, by0, by1);
                    mma16(acc[0][2], a0, bz0, bz1); mma16(acc[0][3], a0, bw0, bw1);
                    mma16(acc[1][0], a1, bx0, bx1); mma16(acc[1][1], a1, by0, by1);
                    mma16(acc[1][2], a1, bz0, bz1); mma16(acc[1][3], a1, bw0, bw1);
                    mma16(acc[2][0], a2, bx0, bx1); mma16(acc[2][1], a2, by0, by1);
                    mma16(acc[2][2], a2, bz0, bz1); mma16(acc[2][3], a2, bw0, bw1);
                    mma16(acc[3][0], a3, bx0, bx1); mma16(acc[3][1], a3, by0, by1);
                    mma16(acc[3][2], a3, bz0, bz1); mma16(acc[3][3], a3, bw0, bw1);
                }
            }
#pragma unroll
            for (int s = 0; s < 4; ++s) {
                const int row = s * 16 + g;
#pragma unroll
                for (int nt = 0; nt < 4; ++nt) {
                    const int col = chunk * 128 + wn1 * 32 + nt * 8 + tig * 2;
                    *reinterpret_cast<__half2*>(qkvh + row * QKV_STR + col) =
                        __floats2half2_rn(acc[s][nt][0], acc[s][nt][1]);
                    *reinterpret_cast<__half2*>(qkvh + (row + 8) * QKV_STR + col) =
                        __floats2half2_rn(acc[s][nt][2], acc[s][nt][3]);
                }
            }
        } else {
            // warps 12-15: load + pack next tile's x into the other buffer
            const int tn = t + GRID_P;
            if (tn < TILES) {
                __half* xsn = (__half*)(smem + XS_OFF + (uint32_t)(cur ^ 1) * XSB_B);
                const int nrow0 = tn * MROWS;
                const int nvr = min(MROWS, R_TOT - nrow0);
                const int ltid = tid - 384;
#pragma unroll
                for (int j = 0; j < 16; ++j) {
                    const int idx = ltid + j * 128;
                    const int m = idx >> 5, gq = idx & 31;
                    float4 v = (m < nvr) ? xv[(size_t)(nrow0 + m) * 32 + gq]
                                         : make_float4(0.f, 0.f, 0.f, 0.f);
                    pack_x4(xsn, m, gq, v);
                }
            }
        }
        __syncthreads();

        // ---- attention (fp32 math, fp16 storage); writes P into xsc ----
        if (tid < BPC * HEADS * VN) {
            const int b = tid / (HEADS * VN);
            const int rem = tid - b * (HEADS * VN);
            const int h = rem / VN;
            const int i = rem - h * VN;
            if (b < valid_items) {
                const int h16 = h * DH;
                const int ri = b * VN + i;
                float qv[DH];
                ld8(qkvh + ri * QKV_STR + h16, qv);
                ld8(qkvh + ri * QKV_STR + h16 + 8, qv + 8);
                float dots[VN];
                float mx = -1e30f;
#pragma unroll
                for (int j = 0; j < VN; ++j) {
                    float kvv[DH];
                    const __half* kr = qkvh + (b * VN + j) * QKV_STR + 128 + h16;
                    ld8(kr, kvv);
                    ld8(kr + 8, kvv + 8);
                    float s = 0.f;
#pragma unroll
                    for (int d = 0; d < DH; ++d) s = fmaf(qv[d], kvv[d], s);
                    float v = s * 0.25f * mk[i * VN + j];
                    dots[j] = v;
                    mx = fmaxf(mx, v);
                }
                float ssum = 0.f;
#pragma unroll
                for (int j = 0; j < VN; ++j) { dots[j] = __expf(dots[j] - mx); ssum += dots[j]; }
                const float inv = 1.0f / ssum;
                float o[DH];
#pragma unroll
                for (int d = 0; d < DH; ++d) o[d] = 0.f;
#pragma unroll
                for (int j = 0; j < VN; ++j) {
                    float vv[DH];
                    const __half* vr = qkvh + (b * VN + j) * QKV_STR + 256 + h16;
                    ld8(vr, vv);
                    ld8(vr + 8, vv + 8);
                    const float w = dots[j];
#pragma unroll
                    for (int d = 0; d < DH; ++d) o[d] = fmaf(w, vv[d], o[d]);
                }
                const int s = ri >> 4, r16 = ri & 15;
                const int gL = r16 & 7, iL = r16 >> 3;
                const int ubase = (s * 8 + h) * 32 + gL * 4;
#pragma unroll
                for (int d = 0; d < DH; d += 2) {
                    const int khi = d >> 3;
                    const int tt = (d >> 1) & 3;
                    const int r = iL + 2 * khi;
                    *reinterpret_cast<__half2*>(xsc + (ubase + tt) * 8 + r * 2) =
                        __floats2half2_rn(o[d] * inv, o[d + 1] * inv);
                }
            }
        }
        __syncthreads();

        // ---- GEMM2: out = P @ W2 + b_out (16 warps, M16N32) ----
        {
            const int wm = wid & 3;
            const int wn = wid >> 2;
            float acc[4][4];
#pragma unroll
            for (int nt = 0; nt < 4; ++nt) {
                const int col = wn * 32 + nt * 8 + tig * 2;
                acc[nt][0] = bouts[col]; acc[nt][1] = bouts[col + 1];
                acc[nt][2] = acc[nt][0]; acc[nt][3] = acc[nt][1];
            }
#pragma unroll
            for (int h = 0; h < 2; ++h)
                gemm2_half(xpc, (const float4*)(smem + WALL_OFF + 3 * 32768 + h * 16384),
                           h, wm, wn, lane, acc);
            const int row = wm * 16 + g;
#pragma unroll
            for (int nt = 0; nt < 4; ++nt) {
                const int col = wn * 32 + nt * 8 + tig * 2;
                if (row < valid_rows) {
                    *reinterpret_cast<float2*>(&out[(size_t)(row0 + row) * C_CH + col]) =
                        make_float2(acc[nt][0], acc[nt][1]);
                }
                if (row + 8 < valid_rows) {
                    *reinterpret_cast<float2*>(&out[(size_t)(row0 + row + 8) * C_CH + col]) =
                        make_float2(acc[nt][2], acc[nt][3]);
                }
            }
        }
        __syncthreads();   // GEMM2 reads done before next iter's pack overwrites xsc
    }
}

// ---------------- launch ----------------
extern "C" void kernel_launch(void* const* d_in, const int* in_sizes, int n_in,
                              void* d_out, int out_size) {
    (void)in_sizes; (void)n_in; (void)out_size;
    const float* x     = (const float*)d_in[0];
    const float* gamma = (const float*)d_in[1];
    const float* beta  = (const float*)d_in[2];
    const float* w_qkv = (const float*)d_in[3];
    const float* w_out = (const float*)d_in[4];
    const float* b_out = (const float*)d_in[5];
    const float* mask  = (const float*)d_in[6];
    float* out = (float*)d_out;

    cudaFuncSetAttribute(ga_main_kernel,
                         cudaFuncAttributeMaxDynamicSharedMemorySize,
                         (int)SMEM_TOTAL);

    ga_stats_kernel<<<STATS_BLOCKS, 128>>>(x);
    ga_prep_kernel<<<1, 128>>>(gamma, beta);
    ga_fold_kernel<<<N3 + C_CH, 128>>>(w_qkv, w_out);
    ga_main_kernel<<<GRID_P, THREADS, SMEM_TOTAL>>>(x, b_out, mask, out);
}